// round 4
// baseline (speedup 1.0000x reference)
#include <cuda_runtime.h>
#include <math.h>

// Problem dims
#define B_   16
#define T_   512
#define C_   2048
#define H_   16
#define HD_  128
#define N3_  6144   // 3*C
#define M_   8192   // B*T

// ---------------- scratch (device globals; no runtime allocation) ----------
__device__ float g_qkv[(size_t)M_ * N3_];          // [B*T, 3*C] fp32  (201 MB)
__device__ float g_qt [(size_t)B_ * H_ * HD_ * T_]; // [B,H,D,T] transposed, RoPE'd (67 MB)
__device__ float g_kt [(size_t)B_ * H_ * HD_ * T_]; // [B,H,D,T] transposed, RoPE'd (67 MB)
__device__ float g_y  [(size_t)M_ * C_];            // attention out [B*T, C] (67 MB)

// ---------------------------------------------------------------------------
// Generic fp32 SGEMM: C[M,N] = A[M,K] @ B[K,N], all row-major.
// 128x128 block tile, K-tile 16, 256 threads, 8x8 per thread, double-buffered.
// Requires M%128==0, N%128==0, K%16==0 (true for all our shapes).
// ---------------------------------------------------------------------------
__global__ __launch_bounds__(256, 2)
void sgemm128x128(const float* __restrict__ A, const float* __restrict__ Bm,
                  float* __restrict__ C, int M, int N, int K)
{
    __shared__ float As[2][16][132];   // transposed: As[k][m]
    __shared__ float Bs[2][16][132];   // Bs[k][n]

    const int tid = threadIdx.x;
    const int tx = tid & 15;           // 0..15 -> n sub
    const int ty = tid >> 4;           // 0..15 -> m sub
    const int m0 = blockIdx.y << 7;
    const int n0 = blockIdx.x << 7;

    // loader indices
    const int ar = tid >> 2;           // 0..63   (A row, and +64)
    const int ak = (tid & 3) << 2;     // 0,4,8,12 (A k-col)
    const int bk = tid >> 5;           // 0..7    (B k-row, and +8)
    const int bc = (tid & 31) << 2;    // 0..124  (B n-col)

    const float* Ap0 = A  + (size_t)(m0 + ar)      * K + ak;
    const float* Ap1 = A  + (size_t)(m0 + ar + 64) * K + ak;
    const float* Bp0 = Bm + (size_t)bk       * N + n0 + bc;
    const float* Bp1 = Bm + (size_t)(bk + 8) * N + n0 + bc;

    float acc[8][8];
#pragma unroll
    for (int i = 0; i < 8; i++)
#pragma unroll
        for (int j = 0; j < 8; j++) acc[i][j] = 0.0f;

    // prefetch tile 0
    float4 pa0 = *(const float4*)(Ap0);
    float4 pa1 = *(const float4*)(Ap1);
    float4 pb0 = *(const float4*)(Bp0);
    float4 pb1 = *(const float4*)(Bp1);

    // store tile 0
    As[0][ak+0][ar] = pa0.x; As[0][ak+1][ar] = pa0.y;
    As[0][ak+2][ar] = pa0.z; As[0][ak+3][ar] = pa0.w;
    As[0][ak+0][ar+64] = pa1.x; As[0][ak+1][ar+64] = pa1.y;
    As[0][ak+2][ar+64] = pa1.z; As[0][ak+3][ar+64] = pa1.w;
    *(float4*)&Bs[0][bk  ][bc] = pb0;
    *(float4*)&Bs[0][bk+8][bc] = pb1;
    __syncthreads();

    const int nt = K >> 4;
    for (int t = 0; t < nt; t++) {
        const int buf = t & 1;
        if (t + 1 < nt) {
            const int k0 = (t + 1) << 4;
            pa0 = *(const float4*)(Ap0 + k0);
            pa1 = *(const float4*)(Ap1 + k0);
            pb0 = *(const float4*)(Bp0 + (size_t)k0 * N);
            pb1 = *(const float4*)(Bp1 + (size_t)k0 * N);
        }
#pragma unroll
        for (int kk = 0; kk < 16; kk++) {
            const float4 a0 = *(const float4*)&As[buf][kk][(ty << 2)];
            const float4 a1 = *(const float4*)&As[buf][kk][64 + (ty << 2)];
            const float4 b0 = *(const float4*)&Bs[buf][kk][(tx << 2)];
            const float4 b1 = *(const float4*)&Bs[buf][kk][64 + (tx << 2)];
            const float av[8] = {a0.x,a0.y,a0.z,a0.w,a1.x,a1.y,a1.z,a1.w};
            const float bv[8] = {b0.x,b0.y,b0.z,b0.w,b1.x,b1.y,b1.z,b1.w};
#pragma unroll
            for (int i = 0; i < 8; i++)
#pragma unroll
                for (int j = 0; j < 8; j++)
                    acc[i][j] = fmaf(av[i], bv[j], acc[i][j]);
        }
        if (t + 1 < nt) {
            const int nb = buf ^ 1;
            As[nb][ak+0][ar] = pa0.x; As[nb][ak+1][ar] = pa0.y;
            As[nb][ak+2][ar] = pa0.z; As[nb][ak+3][ar] = pa0.w;
            As[nb][ak+0][ar+64] = pa1.x; As[nb][ak+1][ar+64] = pa1.y;
            As[nb][ak+2][ar+64] = pa1.z; As[nb][ak+3][ar+64] = pa1.w;
            *(float4*)&Bs[nb][bk  ][bc] = pb0;
            *(float4*)&Bs[nb][bk+8][bc] = pb1;
        }
        __syncthreads();
    }

#pragma unroll
    for (int i = 0; i < 8; i++) {
        const int r = m0 + (ty << 2) + (i & 3) + ((i >> 2) << 6);
        float4 c0, c1;
        c0.x = acc[i][0]; c0.y = acc[i][1]; c0.z = acc[i][2]; c0.w = acc[i][3];
        c1.x = acc[i][4]; c1.y = acc[i][5]; c1.z = acc[i][6]; c1.w = acc[i][7];
        *(float4*)&C[(size_t)r * N + n0 + (tx << 2)]      = c0;
        *(float4*)&C[(size_t)r * N + n0 + 64 + (tx << 2)] = c1;
    }
}

// ---------------------------------------------------------------------------
// RoPE + transpose: reads g_qkv [B,T,3,H,HD], applies RoPE to q and k (first
// 16 dims, pairs (d, d+8)), writes q,k as [B,H,D,T] (d-major) for the
// attention kernel's d-contiguous tile loads.
// grid: B*H*(T/64) blocks, 256 threads. One 64-row tile per block.
// ---------------------------------------------------------------------------
__global__ void rope_transpose_kernel(const float* __restrict__ qkv,
                                      float* __restrict__ qt,
                                      float* __restrict__ kt)
{
    __shared__ float s[64][133];   // pad 133 (odd) -> conflict-free transpose reads
    const int bid = blockIdx.x;
    const int tt = bid & 7;
    const int h  = (bid >> 3) & 15;
    const int b  = bid >> 7;
    const int t0 = tt << 6;
    const int tid = threadIdx.x;
    const int bh = b * H_ + h;

    for (int which = 0; which < 2; which++) {
        float* dst = which ? kt : qt;
        // load 64 rows x 128 cols
#pragma unroll
        for (int p = 0; p < 8; p++) {
            const int idx = tid + (p << 8);
            const int r  = idx >> 5;
            const int c4 = (idx & 31) << 2;
            const float4 v = *(const float4*)
                &qkv[((size_t)((b * T_ + t0 + r) * 3 + which)) * C_ + h * HD_ + c4];
            s[r][c4+0] = v.x; s[r][c4+1] = v.y; s[r][c4+2] = v.z; s[r][c4+3] = v.w;
        }
        __syncthreads();
        // RoPE on first 16 dims: 64 rows x 8 pairs = 512 items, 256 threads
        for (int it = tid; it < 512; it += 256) {
            const int r = it >> 3, d = it & 7;
            const float x1 = s[r][d], x2 = s[r][d + 8];
            const float inv = powf(10000.0f, -(float)d * 0.125f);
            const float ang = (float)(t0 + r) * inv;
            float sn, cs;
            sincosf(ang, &sn, &cs);
            s[r][d]     = x1 * cs - x2 * sn;
            s[r][d + 8] = x2 * cs + x1 * sn;
        }
        __syncthreads();
        // transposed write: [d][t], coalesced along t
        const int tl = tid & 63;
        const size_t base = ((size_t)bh * HD_) * T_ + t0 + tl;
        for (int d = tid >> 6; d < HD_; d += 4)
            dst[base + (size_t)d * T_] = s[tl][d];
        __syncthreads();
    }
}

// ---------------------------------------------------------------------------
// Causal flash attention, fp32. One block per (b, h, 64-row q-tile).
// S tile 64x64 via thread-tiled GEMM on d-major Q/K smem tiles; O (64x128)
// lives in registers (32 floats/thread); online softmax in smem.
// ---------------------------------------------------------------------------
struct AttnSmem {
    float Qts[128][68];   // [d][tq]
    float Kts[128][68];   // [d][tk]
    float Vs [64][132];   // [tk][d]
    float Ss [64][68];    // S then P, in place
    float m_s[64];
    float l_s[64];
    float a_s[64];
};

extern __shared__ char attn_smem_raw[];

__global__ void attention_kernel(const float* __restrict__ qt,
                                 const float* __restrict__ kt,
                                 const float* __restrict__ qkv,
                                 float* __restrict__ y)
{
    AttnSmem& sm = *reinterpret_cast<AttnSmem*>(attn_smem_raw);
    const int bid   = blockIdx.x;
    const int qtile = bid & 7;
    const int h     = (bid >> 3) & 15;
    const int b     = bid >> 7;
    const int bh    = b * H_ + h;
    const int q0    = qtile << 6;
    const int tid   = threadIdx.x;
    const int tx  = tid & 15, ty  = tid >> 4;   // S-gemm map (4x4 per thread)
    const int txp = tid & 31, typ = tid >> 5;   // PV map: rows typ*8+i, cols txp*4+j

    // load Q tile (persistent): Qts[d][0..63]
    {
        const float* src = qt + (size_t)bh * HD_ * T_;
#pragma unroll
        for (int p = 0; p < 8; p++) {
            const int idx = tid + (p << 8);
            const int d  = idx >> 4;
            const int c4 = (idx & 15) << 2;
            *(float4*)&sm.Qts[d][c4] = *(const float4*)&src[(size_t)d * T_ + q0 + c4];
        }
    }
    if (tid < 64) { sm.m_s[tid] = -INFINITY; sm.l_s[tid] = 0.0f; }
    float o[8][4];
#pragma unroll
    for (int i = 0; i < 8; i++)
#pragma unroll
        for (int j = 0; j < 4; j++) o[i][j] = 0.0f;
    __syncthreads();

    const float scale = 0.088388347648318447f;  // 1/sqrt(128)

    for (int ktile = 0; ktile <= qtile; ktile++) {
        const int c0 = ktile << 6;
        // load K tile (d-major) and V tile (t-major, straight from g_qkv)
        {
            const float* ksrc = kt + (size_t)bh * HD_ * T_;
#pragma unroll
            for (int p = 0; p < 8; p++) {
                const int idx = tid + (p << 8);
                const int d  = idx >> 4;
                const int c4 = (idx & 15) << 2;
                *(float4*)&sm.Kts[d][c4] = *(const float4*)&ksrc[(size_t)d * T_ + c0 + c4];
            }
#pragma unroll
            for (int p = 0; p < 8; p++) {
                const int idx = tid + (p << 8);
                const int r  = idx >> 5;
                const int c4 = (idx & 31) << 2;
                *(float4*)&sm.Vs[r][c4] = *(const float4*)
                    &qkv[((size_t)((b * T_ + c0 + r) * 3 + 2)) * C_ + h * HD_ + c4];
            }
        }
        __syncthreads();

        // S = scale * Q K^T  (64x64, 4x4 per thread, k-dim = 128)
        float acc[4][4] = {};
#pragma unroll 8
        for (int d = 0; d < 128; d++) {
            const float4 a  = *(const float4*)&sm.Qts[d][(ty << 2)];
            const float4 bb = *(const float4*)&sm.Kts[d][(tx << 2)];
            acc[0][0]=fmaf(a.x,bb.x,acc[0][0]); acc[0][1]=fmaf(a.x,bb.y,acc[0][1]);
            acc[0][2]=fmaf(a.x,bb.z,acc[0][2]); acc[0][3]=fmaf(a.x,bb.w,acc[0][3]);
            acc[1][0]=fmaf(a.y,bb.x,acc[1][0]); acc[1][1]=fmaf(a.y,bb.y,acc[1][1]);
            acc[1][2]=fmaf(a.y,bb.z,acc[1][2]); acc[1][3]=fmaf(a.y,bb.w,acc[1][3]);
            acc[2][0]=fmaf(a.z,bb.x,acc[2][0]); acc[2][1]=fmaf(a.z,bb.y,acc[2][1]);
            acc[2][2]=fmaf(a.z,bb.z,acc[2][2]); acc[2][3]=fmaf(a.z,bb.w,acc[2][3]);
            acc[3][0]=fmaf(a.w,bb.x,acc[3][0]); acc[3][1]=fmaf(a.w,bb.y,acc[3][1]);
            acc[3][2]=fmaf(a.w,bb.z,acc[3][2]); acc[3][3]=fmaf(a.w,bb.w,acc[3][3]);
        }
#pragma unroll
        for (int i = 0; i < 4; i++) {
            float4 w;
            w.x = acc[i][0]*scale; w.y = acc[i][1]*scale;
            w.z = acc[i][2]*scale; w.w = acc[i][3]*scale;
            *(float4*)&sm.Ss[(ty << 2) + i][(tx << 2)] = w;
        }
        __syncthreads();

        // online softmax: 4 threads per row, 16 cols each
        {
            const int r = tid >> 2, sub = tid & 3;
            const bool diag = (ktile == qtile);
            float vals[16];
            float mx = -INFINITY;
#pragma unroll
            for (int k = 0; k < 16; k++) {
                const int c = (sub << 4) + k;
                float v = sm.Ss[r][c];
                if (diag && c > r) v = -INFINITY;
                vals[k] = v;
                mx = fmaxf(mx, v);
            }
            mx = fmaxf(mx, __shfl_xor_sync(0xffffffffu, mx, 1));
            mx = fmaxf(mx, __shfl_xor_sync(0xffffffffu, mx, 2));
            const float m_old = sm.m_s[r];
            const float m_new = fmaxf(m_old, mx);
            float sum = 0.0f;
#pragma unroll
            for (int k = 0; k < 16; k++) {
                const float pexp = __expf(vals[k] - m_new);  // -inf -> 0
                sum += pexp;
                sm.Ss[r][(sub << 4) + k] = pexp;
            }
            sum += __shfl_xor_sync(0xffffffffu, sum, 1);
            sum += __shfl_xor_sync(0xffffffffu, sum, 2);
            if (sub == 0) {
                const float alpha = __expf(m_old - m_new);   // first iter: 0
                sm.m_s[r] = m_new;
                sm.l_s[r] = sm.l_s[r] * alpha + sum;
                sm.a_s[r] = alpha;
            }
        }
        __syncthreads();

        // O = alpha*O + P @ V
        {
            float al[8];
#pragma unroll
            for (int i = 0; i < 8; i++) al[i] = sm.a_s[(typ << 3) + i];
#pragma unroll
            for (int i = 0; i < 8; i++)
#pragma unroll
                for (int j = 0; j < 4; j++) o[i][j] *= al[i];

#pragma unroll 4
            for (int j = 0; j < 64; j++) {
                const float4 v = *(const float4*)&sm.Vs[j][(txp << 2)];
#pragma unroll
                for (int i = 0; i < 8; i++) {
                    const float p = sm.Ss[(typ << 3) + i][j];  // warp-broadcast
                    o[i][0] = fmaf(p, v.x, o[i][0]);
                    o[i][1] = fmaf(p, v.y, o[i][1]);
                    o[i][2] = fmaf(p, v.z, o[i][2]);
                    o[i][3] = fmaf(p, v.w, o[i][3]);
                }
            }
        }
        __syncthreads();
    }

    // normalize + write y [B*T, C] (head-interleaved row-major)
#pragma unroll
    for (int i = 0; i < 8; i++) {
        const int r = (typ << 3) + i;
        const float invl = 1.0f / sm.l_s[r];
        float4 w;
        w.x = o[i][0]*invl; w.y = o[i][1]*invl;
        w.z = o[i][2]*invl; w.w = o[i][3]*invl;
        *(float4*)&y[(size_t)(b * T_ + q0 + r) * C_ + h * HD_ + (txp << 2)] = w;
    }
}

// ---------------------------------------------------------------------------
extern "C" void kernel_launch(void* const* d_in, const int* in_sizes, int n_in,
                              void* d_out, int out_size)
{
    const float* x    = (const float*)d_in[0];   // [16,512,2048]
    const float* Wqkv = (const float*)d_in[1];   // [2048,6144]
    const float* Wout = (const float*)d_in[2];   // [2048,2048]
    float* out = (float*)d_out;                  // [16,512,2048]

    float *qkv, *qt, *kt, *y;
    cudaGetSymbolAddress((void**)&qkv, g_qkv);
    cudaGetSymbolAddress((void**)&qt,  g_qt);
    cudaGetSymbolAddress((void**)&kt,  g_kt);
    cudaGetSymbolAddress((void**)&y,   g_y);

    // 1) qkv = x @ Wqkv
    sgemm128x128<<<dim3(N3_ / 128, M_ / 128), 256>>>(x, Wqkv, qkv, M_, N3_, C_);

    // 2) RoPE + transpose q,k into [B,H,D,T]
    rope_transpose_kernel<<<B_ * H_ * (T_ / 64), 256>>>(qkv, qt, kt);

    // 3) causal flash attention -> y [B*T, C]
    const int smem = (int)sizeof(AttnSmem);
    cudaFuncSetAttribute(attention_kernel,
                         cudaFuncAttributeMaxDynamicSharedMemorySize, smem);
    attention_kernel<<<B_ * H_ * (T_ / 64), 256, smem>>>(qt, kt, qkv, y);

    // 4) out = y @ Wout
    sgemm128x128<<<dim3(C_ / 128, M_ / 128), 256>>>(y, Wout, out, M_, C_, C_);
}

// round 7
// speedup vs baseline: 2.1423x; 2.1423x over previous
#include <cuda_runtime.h>
#include <cuda_bf16.h>
#include <math.h>
#include <stdint.h>

// Problem dims
#define B_   16
#define T_   512
#define C_   2048
#define H_   16
#define HD_  128
#define N3_  6144   // 3*C
#define M_   8192   // B*T
#define K3_  6144   // split-K (hi|lo|hi concatenation) for both GEMMs
#define KC_  64     // bf16 K-chunk per stage (128 bytes per row)
#define NT_  (K3_ / KC_)   // 96 chunks

// ---------------- scratch (device globals; no runtime allocation) ----------
__device__ float          g_qkv  [(size_t)M_ * N3_];            // [B*T, 3*C] fp32
__device__ float          g_qt   [(size_t)B_ * H_ * HD_ * T_];  // [B,H,D,T]
__device__ float          g_kt   [(size_t)B_ * H_ * HD_ * T_];  // [B,H,D,T]
__device__ __nv_bfloat16  g_a2   [(size_t)M_ * K3_];            // [M, 3K] = [x_hi | x_lo | x_hi]
__device__ __nv_bfloat16  g_b2q  [(size_t)N3_ * K3_];           // [6144, 3K] = [W_hi | W_hi | W_lo] (transposed)
__device__ __nv_bfloat16  g_b2o  [(size_t)C_ * K3_];            // [2048, 3K]
__device__ __nv_bfloat16  g_y2   [(size_t)M_ * K3_];            // attention out, split layout

// ===================== helpers ==============================================
__device__ __forceinline__ uint32_t smem_u32(const void* p) {
    uint32_t a;
    asm("{ .reg .u64 t; cvta.to.shared.u64 t, %1; cvt.u32.u64 %0, t; }" : "=r"(a) : "l"(p));
    return a;
}
__device__ __forceinline__ void cp16(uint32_t dst, const void* src) {
    asm volatile("cp.async.cg.shared.global [%0], [%1], 16;" :: "r"(dst), "l"(src));
}
#define CP_COMMIT()  asm volatile("cp.async.commit_group;" ::: "memory")
#define CP_WAIT0()   asm volatile("cp.async.wait_group 0;" ::: "memory")

#define SW128(off) ((off) ^ (((off) >> 3) & 0x70))

__device__ __forceinline__ uint32_t pack2(float a, float b) {
    __nv_bfloat162 t = __floats2bfloat162_rn(a, b);
    return *reinterpret_cast<uint32_t*>(&t);
}
__device__ __forceinline__ float bf16_round(float a) {
    return __bfloat162float(__float2bfloat16(a));
}

// ===================== conversion kernels ===================================
// x [M, 2048] fp32 -> A2 [M, 6144] bf16 as [hi | lo | hi]
__global__ void conv_a_kernel(const float* __restrict__ X, __nv_bfloat16* __restrict__ A2)
{
    const int idx = blockIdx.x * 256 + threadIdx.x;   // one float4 each
    const int e = idx << 2;
    const int m = e >> 11;            // /2048
    const int k = e & 2047;
    const float4 v = *(const float4*)&X[(size_t)e];
    const float h0 = bf16_round(v.x), h1 = bf16_round(v.y);
    const float h2 = bf16_round(v.z), h3 = bf16_round(v.w);
    uint2 hp, lp;
    hp.x = pack2(h0, h1); hp.y = pack2(h2, h3);
    lp.x = pack2(v.x - h0, v.y - h1); lp.y = pack2(v.z - h2, v.w - h3);
    const size_t ro = (size_t)m * K3_;
    *(uint2*)&A2[ro + k]        = hp;
    *(uint2*)&A2[ro + 2048 + k] = lp;
    *(uint2*)&A2[ro + 4096 + k] = hp;
}

// W [2048, N] fp32 -> B2 [N, 6144] bf16 (transposed) as [hi | hi | lo]
__global__ void conv_w_kernel(const float* __restrict__ W, __nv_bfloat16* __restrict__ B2, int N)
{
    __shared__ float tile[32][33];
    const int n0 = blockIdx.x << 5;
    const int k0 = blockIdx.y << 5;
    const int tid = threadIdx.x;
    const int c = tid & 31, rb = tid >> 5;
#pragma unroll
    for (int j = 0; j < 4; j++) {
        const int r = rb + (j << 3);
        tile[r][c] = W[(size_t)(k0 + r) * N + n0 + c];
    }
    __syncthreads();
#pragma unroll
    for (int j = 0; j < 4; j++) {
        const int nl = rb + (j << 3);
        const int kl = c;
        const float v = tile[kl][nl];
        const float h = bf16_round(v);
        const __nv_bfloat16 hb = __float2bfloat16(h);
        const __nv_bfloat16 lb = __float2bfloat16(v - h);
        const size_t ro = (size_t)(n0 + nl) * K3_ + k0 + kl;
        B2[ro]        = hb;
        B2[ro + 2048] = hb;
        B2[ro + 4096] = lb;
    }
}

// ===================== bf16 mma.sync GEMM ===================================
// C[M, N] fp32 = A2[M, 6144] @ B2[N, 6144]^T  (both K-major bf16)
// 128x128 CTA tile, 8 warps (2x4), warp tile 64x32, K-chunk 64,
// cp.async double buffer, ldmatrix fragments, mma.sync.m16n8k16.
#define G_SMEM_BYTES (2 * 32768)   // per stage: A 16KB + B 16KB

__global__ __launch_bounds__(256, 2)
void gemm_mma(const __nv_bfloat16* __restrict__ A,
              const __nv_bfloat16* __restrict__ Bt,
              float* __restrict__ C, int N)
{
    extern __shared__ char sm[];
    const uint32_t sbase = smem_u32(sm);
    const int tid  = threadIdx.x;
    const int lane = tid & 31;
    const int w    = tid >> 5;
    const int wm   = w >> 2;        // 0..1
    const int wn   = w & 3;         // 0..3
    const int m0 = blockIdx.y << 7;
    const int n0 = blockIdx.x << 7;

    // ---- cp.async loader setup: per array 1024x16B per chunk, 4 per thread
    const int r0  = tid >> 3;       // 0..31 (row, +32*i)
    const int c16 = tid & 7;        // 16B column within 128B row
    const uint32_t dsw = SW128((uint32_t)(r0 * 128 + c16 * 16));
    const char* Ag = (const char*)(A  + (size_t)(m0 + r0) * K3_) + c16 * 16;
    const char* Bg = (const char*)(Bt + (size_t)(n0 + r0) * K3_) + c16 * 16;
    const size_t rstep = (size_t)32 * K3_ * 2;   // 32 rows in bytes

    // ---- fragment address setup (SW128-swizzled, conflict-free ldmatrix)
    const int l15 = lane & 15;            // A: row within 16
    const int acg = (lane >> 4) & 1;      // A: k-group (0/8)
    const int l7  = lane & 7;             // B: row within 8
    const int bcg = (lane >> 3) & 1;      // B: k-group
    const uint32_t xrA = (uint32_t)((l15 & 7) << 4);
    const uint32_t xrB = (uint32_t)(l7 << 4);
    uint32_t baseA[4], baseB[4];
#pragma unroll
    for (int mt = 0; mt < 4; mt++)
        baseA[mt] = (uint32_t)((wm * 64 + mt * 16 + l15) * 128);
#pragma unroll
    for (int nt = 0; nt < 4; nt++)
        baseB[nt] = (uint32_t)(16384 + (wn * 32 + nt * 8 + l7) * 128);

    float acc[4][4][4];
#pragma unroll
    for (int mt = 0; mt < 4; mt++)
#pragma unroll
        for (int nt = 0; nt < 4; nt++)
#pragma unroll
            for (int i = 0; i < 4; i++) acc[mt][nt][i] = 0.0f;

    // ---- prologue: stage chunk 0 into buffer 0
    {
        const uint32_t sA = sbase, sB = sbase + 16384;
#pragma unroll
        for (int i = 0; i < 4; i++) {
            cp16(sA + dsw + i * 4096, Ag + (size_t)i * rstep);
            cp16(sB + dsw + i * 4096, Bg + (size_t)i * rstep);
        }
        CP_COMMIT();
    }

    for (int t = 0; t < NT_; t++) {
        CP_WAIT0();
        __syncthreads();
        if (t + 1 < NT_) {
            const uint32_t so = ((t + 1) & 1) * 32768u;
            const char* ga = Ag + (size_t)(t + 1) * 128;
            const char* gb = Bg + (size_t)(t + 1) * 128;
#pragma unroll
            for (int i = 0; i < 4; i++) {
                cp16(sbase + so + dsw + i * 4096,          ga + (size_t)i * rstep);
                cp16(sbase + so + 16384 + dsw + i * 4096,  gb + (size_t)i * rstep);
            }
            CP_COMMIT();
        }
        const uint32_t bufo = sbase + (t & 1) * 32768u;
#pragma unroll
        for (int ks = 0; ks < 4; ks++) {
            const uint32_t axo = ((uint32_t)(ks * 32 + acg * 16)) ^ xrA;
            const uint32_t bxo = ((uint32_t)(ks * 32 + bcg * 16)) ^ xrB;
            uint32_t a[4][4], b[4][2];
#pragma unroll
            for (int mt = 0; mt < 4; mt++)
                asm volatile("ldmatrix.sync.aligned.m8n8.x4.shared.b16 {%0,%1,%2,%3}, [%4];"
                    : "=r"(a[mt][0]), "=r"(a[mt][1]), "=r"(a[mt][2]), "=r"(a[mt][3])
                    : "r"(bufo + baseA[mt] + axo));
#pragma unroll
            for (int nt = 0; nt < 4; nt++)
                asm volatile("ldmatrix.sync.aligned.m8n8.x2.shared.b16 {%0,%1}, [%2];"
                    : "=r"(b[nt][0]), "=r"(b[nt][1])
                    : "r"(bufo + baseB[nt] + bxo));
#pragma unroll
            for (int mt = 0; mt < 4; mt++)
#pragma unroll
                for (int nt = 0; nt < 4; nt++)
                    asm volatile(
                        "mma.sync.aligned.m16n8k16.row.col.f32.bf16.bf16.f32 "
                        "{%0,%1,%2,%3}, {%4,%5,%6,%7}, {%8,%9}, {%0,%1,%2,%3};"
                        : "+f"(acc[mt][nt][0]), "+f"(acc[mt][nt][1]),
                          "+f"(acc[mt][nt][2]), "+f"(acc[mt][nt][3])
                        : "r"(a[mt][0]), "r"(a[mt][1]), "r"(a[mt][2]), "r"(a[mt][3]),
                          "r"(b[nt][0]), "r"(b[nt][1]));
        }
    }

    // ---- epilogue
    const int gid = lane >> 2, tig = lane & 3;
#pragma unroll
    for (int mt = 0; mt < 4; mt++) {
        const int r = m0 + wm * 64 + mt * 16 + gid;
#pragma unroll
        for (int nt = 0; nt < 4; nt++) {
            const int cc = n0 + wn * 32 + nt * 8 + 2 * tig;
            float2 v0 = make_float2(acc[mt][nt][0], acc[mt][nt][1]);
            float2 v1 = make_float2(acc[mt][nt][2], acc[mt][nt][3]);
            *(float2*)&C[(size_t)r * N + cc]       = v0;
            *(float2*)&C[(size_t)(r + 8) * N + cc] = v1;
        }
    }
}

// ===================== RoPE + transpose =====================================
__global__ void rope_transpose_kernel(const float* __restrict__ qkv,
                                      float* __restrict__ qt,
                                      float* __restrict__ kt)
{
    __shared__ float s[64][133];
    const int bid = blockIdx.x;
    const int tt = bid & 7;
    const int h  = (bid >> 3) & 15;
    const int b  = bid >> 7;
    const int t0 = tt << 6;
    const int tid = threadIdx.x;
    const int bh = b * H_ + h;

    for (int which = 0; which < 2; which++) {
        float* dst = which ? kt : qt;
#pragma unroll
        for (int p = 0; p < 8; p++) {
            const int idx = tid + (p << 8);
            const int r  = idx >> 5;
            const int c4 = (idx & 31) << 2;
            const float4 v = *(const float4*)
                &qkv[((size_t)((b * T_ + t0 + r) * 3 + which)) * C_ + h * HD_ + c4];
            s[r][c4+0] = v.x; s[r][c4+1] = v.y; s[r][c4+2] = v.z; s[r][c4+3] = v.w;
        }
        __syncthreads();
        for (int it = tid; it < 512; it += 256) {
            const int r = it >> 3, d = it & 7;
            const float x1 = s[r][d], x2 = s[r][d + 8];
            const float inv = powf(10000.0f, -(float)d * 0.125f);
            const float ang = (float)(t0 + r) * inv;
            float sn, cs;
            sincosf(ang, &sn, &cs);
            s[r][d]     = x1 * cs - x2 * sn;
            s[r][d + 8] = x2 * cs + x1 * sn;
        }
        __syncthreads();
        const int tl = tid & 63;
        const size_t base = ((size_t)bh * HD_) * T_ + t0 + tl;
        for (int d = tid >> 6; d < HD_; d += 4)
            dst[base + (size_t)d * T_] = s[tl][d];
        __syncthreads();
    }
}

// ===================== attention (epilogue -> bf16 hi/lo split) =============
struct AttnSmem {
    float Qts[128][68];
    float Kts[128][68];
    float Vs [64][132];
    float Ss [64][68];
    float m_s[64];
    float l_s[64];
    float a_s[64];
};
extern __shared__ char attn_smem_raw[];

__global__ void attention_kernel(const float* __restrict__ qt,
                                 const float* __restrict__ kt,
                                 const float* __restrict__ qkv,
                                 __nv_bfloat16* __restrict__ y2)
{
    AttnSmem& sm = *reinterpret_cast<AttnSmem*>(attn_smem_raw);
    const int bid   = blockIdx.x;
    const int qtile = bid & 7;
    const int h     = (bid >> 3) & 15;
    const int b     = bid >> 7;
    const int bh    = b * H_ + h;
    const int q0    = qtile << 6;
    const int tid   = threadIdx.x;
    const int tx  = tid & 15, ty  = tid >> 4;
    const int txp = tid & 31, typ = tid >> 5;

    {
        const float* src = qt + (size_t)bh * HD_ * T_;
#pragma unroll
        for (int p = 0; p < 8; p++) {
            const int idx = tid + (p << 8);
            const int d  = idx >> 4;
            const int c4 = (idx & 15) << 2;
            *(float4*)&sm.Qts[d][c4] = *(const float4*)&src[(size_t)d * T_ + q0 + c4];
        }
    }
    if (tid < 64) { sm.m_s[tid] = -INFINITY; sm.l_s[tid] = 0.0f; }
    float o[8][4];
#pragma unroll
    for (int i = 0; i < 8; i++)
#pragma unroll
        for (int j = 0; j < 4; j++) o[i][j] = 0.0f;
    __syncthreads();

    const float scale = 0.088388347648318447f;

    for (int ktile = 0; ktile <= qtile; ktile++) {
        const int c0 = ktile << 6;
        {
            const float* ksrc = kt + (size_t)bh * HD_ * T_;
#pragma unroll
            for (int p = 0; p < 8; p++) {
                const int idx = tid + (p << 8);
                const int d  = idx >> 4;
                const int c4 = (idx & 15) << 2;
                *(float4*)&sm.Kts[d][c4] = *(const float4*)&ksrc[(size_t)d * T_ + c0 + c4];
            }
#pragma unroll
            for (int p = 0; p < 8; p++) {
                const int idx = tid + (p << 8);
                const int r  = idx >> 5;
                const int c4 = (idx & 31) << 2;
                *(float4*)&sm.Vs[r][c4] = *(const float4*)
                    &qkv[((size_t)((b * T_ + c0 + r) * 3 + 2)) * C_ + h * HD_ + c4];
            }
        }
        __syncthreads();

        float acc[4][4] = {};
#pragma unroll 8
        for (int d = 0; d < 128; d++) {
            const float4 a  = *(const float4*)&sm.Qts[d][(ty << 2)];
            const float4 bb = *(const float4*)&sm.Kts[d][(tx << 2)];
            acc[0][0]=fmaf(a.x,bb.x,acc[0][0]); acc[0][1]=fmaf(a.x,bb.y,acc[0][1]);
            acc[0][2]=fmaf(a.x,bb.z,acc[0][2]); acc[0][3]=fmaf(a.x,bb.w,acc[0][3]);
            acc[1][0]=fmaf(a.y,bb.x,acc[1][0]); acc[1][1]=fmaf(a.y,bb.y,acc[1][1]);
            acc[1][2]=fmaf(a.y,bb.z,acc[1][2]); acc[1][3]=fmaf(a.y,bb.w,acc[1][3]);
            acc[2][0]=fmaf(a.z,bb.x,acc[2][0]); acc[2][1]=fmaf(a.z,bb.y,acc[2][1]);
            acc[2][2]=fmaf(a.z,bb.z,acc[2][2]); acc[2][3]=fmaf(a.z,bb.w,acc[2][3]);
            acc[3][0]=fmaf(a.w,bb.x,acc[3][0]); acc[3][1]=fmaf(a.w,bb.y,acc[3][1]);
            acc[3][2]=fmaf(a.w,bb.z,acc[3][2]); acc[3][3]=fmaf(a.w,bb.w,acc[3][3]);
        }
#pragma unroll
        for (int i = 0; i < 4; i++) {
            float4 w;
            w.x = acc[i][0]*scale; w.y = acc[i][1]*scale;
            w.z = acc[i][2]*scale; w.w = acc[i][3]*scale;
            *(float4*)&sm.Ss[(ty << 2) + i][(tx << 2)] = w;
        }
        __syncthreads();

        {
            const int r = tid >> 2, sub = tid & 3;
            const bool diag = (ktile == qtile);
            float vals[16];
            float mx = -INFINITY;
#pragma unroll
            for (int k = 0; k < 16; k++) {
                const int c = (sub << 4) + k;
                float v = sm.Ss[r][c];
                if (diag && c > r) v = -INFINITY;
                vals[k] = v;
                mx = fmaxf(mx, v);
            }
            mx = fmaxf(mx, __shfl_xor_sync(0xffffffffu, mx, 1));
            mx = fmaxf(mx, __shfl_xor_sync(0xffffffffu, mx, 2));
            const float m_old = sm.m_s[r];
            const float m_new = fmaxf(m_old, mx);
            float sum = 0.0f;
#pragma unroll
            for (int k = 0; k < 16; k++) {
                const float pexp = __expf(vals[k] - m_new);
                sum += pexp;
                sm.Ss[r][(sub << 4) + k] = pexp;
            }
            sum += __shfl_xor_sync(0xffffffffu, sum, 1);
            sum += __shfl_xor_sync(0xffffffffu, sum, 2);
            if (sub == 0) {
                const float alpha = __expf(m_old - m_new);
                sm.m_s[r] = m_new;
                sm.l_s[r] = sm.l_s[r] * alpha + sum;
                sm.a_s[r] = alpha;
            }
        }
        __syncthreads();

        {
            float al[8];
#pragma unroll
            for (int i = 0; i < 8; i++) al[i] = sm.a_s[(typ << 3) + i];
#pragma unroll
            for (int i = 0; i < 8; i++)
#pragma unroll
                for (int j = 0; j < 4; j++) o[i][j] *= al[i];

#pragma unroll 4
            for (int j = 0; j < 64; j++) {
                const float4 v = *(const float4*)&sm.Vs[j][(txp << 2)];
#pragma unroll
                for (int i = 0; i < 8; i++) {
                    const float p = sm.Ss[(typ << 3) + i][j];
                    o[i][0] = fmaf(p, v.x, o[i][0]);
                    o[i][1] = fmaf(p, v.y, o[i][1]);
                    o[i][2] = fmaf(p, v.z, o[i][2]);
                    o[i][3] = fmaf(p, v.w, o[i][3]);
                }
            }
        }
        __syncthreads();
    }

    // epilogue: normalize + write bf16 hi/lo split into y2 [M, 6144]
    const int kcol = h * HD_ + (txp << 2);
#pragma unroll
    for (int i = 0; i < 8; i++) {
        const int r = (typ << 3) + i;
        const float invl = 1.0f / sm.l_s[r];
        const float v0 = o[i][0]*invl, v1 = o[i][1]*invl;
        const float v2 = o[i][2]*invl, v3 = o[i][3]*invl;
        const float h0 = bf16_round(v0), h1 = bf16_round(v1);
        const float h2 = bf16_round(v2), h3 = bf16_round(v3);
        uint2 hp, lp;
        hp.x = pack2(h0, h1); hp.y = pack2(h2, h3);
        lp.x = pack2(v0 - h0, v1 - h1); lp.y = pack2(v2 - h2, v3 - h3);
        const size_t ro = (size_t)(b * T_ + q0 + r) * K3_;
        *(uint2*)&y2[ro + kcol]        = hp;
        *(uint2*)&y2[ro + 2048 + kcol] = lp;
        *(uint2*)&y2[ro + 4096 + kcol] = hp;
    }
}

// ---------------------------------------------------------------------------
extern "C" void kernel_launch(void* const* d_in, const int* in_sizes, int n_in,
                              void* d_out, int out_size)
{
    const float* x    = (const float*)d_in[0];   // [16,512,2048]
    const float* Wqkv = (const float*)d_in[1];   // [2048,6144]
    const float* Wout = (const float*)d_in[2];   // [2048,2048]
    float* out = (float*)d_out;                  // [16,512,2048]

    float *qkv, *qt, *kt;
    __nv_bfloat16 *a2, *b2q, *b2o, *y2;
    cudaGetSymbolAddress((void**)&qkv, g_qkv);
    cudaGetSymbolAddress((void**)&qt,  g_qt);
    cudaGetSymbolAddress((void**)&kt,  g_kt);
    cudaGetSymbolAddress((void**)&a2,  g_a2);
    cudaGetSymbolAddress((void**)&b2q, g_b2q);
    cudaGetSymbolAddress((void**)&b2o, g_b2o);
    cudaGetSymbolAddress((void**)&y2,  g_y2);

    // 0) bf16 hi/lo conversions
    conv_a_kernel<<<(M_ * C_) / 1024, 256>>>(x, a2);
    conv_w_kernel<<<dim3(N3_ / 32, C_ / 32), 256>>>(Wqkv, b2q, N3_);
    conv_w_kernel<<<dim3(C_ / 32,  C_ / 32), 256>>>(Wout, b2o, C_);

    cudaFuncSetAttribute(gemm_mma, cudaFuncAttributeMaxDynamicSharedMemorySize, G_SMEM_BYTES);

    // 1) qkv = x @ Wqkv   (mma.sync bf16 3-split, K'=6144)
    gemm_mma<<<dim3(N3_ / 128, M_ / 128), 256, G_SMEM_BYTES>>>(a2, b2q, qkv, N3_);

    // 2) RoPE + transpose q,k into [B,H,D,T]
    rope_transpose_kernel<<<B_ * H_ * (T_ / 64), 256>>>(qkv, qt, kt);

    // 3) causal flash attention -> y2 (bf16 split layout)
    const int smem = (int)sizeof(AttnSmem);
    cudaFuncSetAttribute(attention_kernel,
                         cudaFuncAttributeMaxDynamicSharedMemorySize, smem);
    attention_kernel<<<B_ * H_ * (T_ / 64), 256, smem>>>(qt, kt, qkv, y2);

    // 4) out = y @ Wout   (mma.sync bf16 3-split)
    gemm_mma<<<dim3(C_ / 128, M_ / 128), 256, G_SMEM_BYTES>>>(y2, b2o, out, C_);
}

// round 11
// speedup vs baseline: 2.4905x; 1.1626x over previous
#include <cuda_runtime.h>
#include <cuda_bf16.h>
#include <math.h>
#include <stdint.h>

// Problem dims
#define B_   16
#define T_   512
#define C_   2048
#define H_   16
#define HD_  128
#define N3_  6144   // 3*C
#define M_   8192   // B*T
#define K3_  6144   // split-K (hi|lo|hi concatenation) for both GEMMs
#define KC_  64
#define NT_  (K3_ / KC_)

// ---------------- scratch (device globals; no runtime allocation) ----------
__device__ float          g_qkv  [(size_t)M_ * N3_];            // [B*T, 3*C] fp32
__device__ __nv_bfloat16  g_q2   [(size_t)B_ * H_ * T_ * 256];  // [B,H,T, hi128|lo128]
__device__ __nv_bfloat16  g_k2   [(size_t)B_ * H_ * T_ * 256];
__device__ __nv_bfloat16  g_v2   [(size_t)B_ * H_ * T_ * 256];
__device__ __nv_bfloat16  g_a2   [(size_t)M_ * K3_];            // [M, 3K] = [x_hi | x_lo | x_hi]
__device__ __nv_bfloat16  g_b2q  [(size_t)N3_ * K3_];           // [6144, 3K] = [W_hi | W_hi | W_lo]
__device__ __nv_bfloat16  g_b2o  [(size_t)C_ * K3_];            // [2048, 3K]
__device__ __nv_bfloat16  g_y2   [(size_t)M_ * K3_];            // attention out, split layout

// ===================== helpers ==============================================
__device__ __forceinline__ uint32_t smem_u32(const void* p) {
    uint32_t a;
    asm("{ .reg .u64 t; cvta.to.shared.u64 t, %1; cvt.u32.u64 %0, t; }" : "=r"(a) : "l"(p));
    return a;
}
__device__ __forceinline__ void cp16(uint32_t dst, const void* src) {
    asm volatile("cp.async.cg.shared.global [%0], [%1], 16;" :: "r"(dst), "l"(src));
}
#define CP_COMMIT()  asm volatile("cp.async.commit_group;" ::: "memory")
#define CP_WAIT0()   asm volatile("cp.async.wait_group 0;" ::: "memory")
#define SW128(off) ((off) ^ (((off) >> 3) & 0x70))

#define LDX4(a, addr) asm volatile( \
    "ldmatrix.sync.aligned.m8n8.x4.shared.b16 {%0,%1,%2,%3}, [%4];" \
    : "=r"((a)[0]), "=r"((a)[1]), "=r"((a)[2]), "=r"((a)[3]) : "r"(addr))
#define LDX2(bq, addr) asm volatile( \
    "ldmatrix.sync.aligned.m8n8.x2.shared.b16 {%0,%1}, [%2];" \
    : "=r"((bq)[0]), "=r"((bq)[1]) : "r"(addr))
#define LDX2T(bq, addr) asm volatile( \
    "ldmatrix.sync.aligned.m8n8.x2.trans.shared.b16 {%0,%1}, [%2];" \
    : "=r"((bq)[0]), "=r"((bq)[1]) : "r"(addr))
#define MMA16816(c, a, bq) asm volatile( \
    "mma.sync.aligned.m16n8k16.row.col.f32.bf16.bf16.f32 " \
    "{%0,%1,%2,%3}, {%4,%5,%6,%7}, {%8,%9}, {%0,%1,%2,%3};" \
    : "+f"((c)[0]), "+f"((c)[1]), "+f"((c)[2]), "+f"((c)[3]) \
    : "r"((a)[0]), "r"((a)[1]), "r"((a)[2]), "r"((a)[3]), "r"((bq)[0]), "r"((bq)[1]))

__device__ __forceinline__ uint32_t pack2(float a, float b) {
    __nv_bfloat162 t = __floats2bfloat162_rn(a, b);
    return *reinterpret_cast<uint32_t*>(&t);
}
__device__ __forceinline__ float bf16_round(float a) {
    return __bfloat162float(__float2bfloat16(a));
}

// ===================== conversion kernels ===================================
__global__ void conv_a_kernel(const float* __restrict__ X, __nv_bfloat16* __restrict__ A2)
{
    const int idx = blockIdx.x * 256 + threadIdx.x;
    const int e = idx << 2;
    const int m = e >> 11;
    const int k = e & 2047;
    const float4 v = *(const float4*)&X[(size_t)e];
    const float h0 = bf16_round(v.x), h1 = bf16_round(v.y);
    const float h2 = bf16_round(v.z), h3 = bf16_round(v.w);
    uint2 hp, lp;
    hp.x = pack2(h0, h1); hp.y = pack2(h2, h3);
    lp.x = pack2(v.x - h0, v.y - h1); lp.y = pack2(v.z - h2, v.w - h3);
    const size_t ro = (size_t)m * K3_;
    *(uint2*)&A2[ro + k]        = hp;
    *(uint2*)&A2[ro + 2048 + k] = lp;
    *(uint2*)&A2[ro + 4096 + k] = hp;
}

__global__ void conv_w_kernel(const float* __restrict__ W, __nv_bfloat16* __restrict__ B2, int N)
{
    __shared__ float tile[32][33];
    const int n0 = blockIdx.x << 5;
    const int k0 = blockIdx.y << 5;
    const int tid = threadIdx.x;
    const int c = tid & 31, rb = tid >> 5;
#pragma unroll
    for (int j = 0; j < 4; j++) {
        const int r = rb + (j << 3);
        tile[r][c] = W[(size_t)(k0 + r) * N + n0 + c];
    }
    __syncthreads();
#pragma unroll
    for (int j = 0; j < 4; j++) {
        const int nl = rb + (j << 3);
        const int kl = c;
        const float v = tile[kl][nl];
        const float h = bf16_round(v);
        const __nv_bfloat16 hb = __float2bfloat16(h);
        const __nv_bfloat16 lb = __float2bfloat16(v - h);
        const size_t ro = (size_t)(n0 + nl) * K3_ + k0 + kl;
        B2[ro]        = hb;
        B2[ro + 2048] = hb;
        B2[ro + 4096] = lb;
    }
}

// ===================== bf16 mma.sync GEMM ===================================
#define G_SMEM_BYTES (2 * 32768)

__global__ __launch_bounds__(256, 2)
void gemm_mma(const __nv_bfloat16* __restrict__ A,
              const __nv_bfloat16* __restrict__ Bt,
              float* __restrict__ C, int N)
{
    extern __shared__ char sm[];
    const uint32_t sbase = smem_u32(sm);
    const int tid  = threadIdx.x;
    const int lane = tid & 31;
    const int w    = tid >> 5;
    const int wm   = w >> 2;
    const int wn   = w & 3;
    const int m0 = blockIdx.y << 7;
    const int n0 = blockIdx.x << 7;

    const int r0  = tid >> 3;
    const int c16 = tid & 7;
    const uint32_t dsw = SW128((uint32_t)(r0 * 128 + c16 * 16));
    const char* Ag = (const char*)(A  + (size_t)(m0 + r0) * K3_) + c16 * 16;
    const char* Bg = (const char*)(Bt + (size_t)(n0 + r0) * K3_) + c16 * 16;
    const size_t rstep = (size_t)32 * K3_ * 2;

    const int l15 = lane & 15;
    const int acg = (lane >> 4) & 1;
    const int l7  = lane & 7;
    const int bcg = (lane >> 3) & 1;
    const uint32_t xrA = (uint32_t)((l15 & 7) << 4);
    const uint32_t xrB = (uint32_t)(l7 << 4);
    uint32_t baseA[4], baseB[4];
#pragma unroll
    for (int mt = 0; mt < 4; mt++)
        baseA[mt] = (uint32_t)((wm * 64 + mt * 16 + l15) * 128);
#pragma unroll
    for (int nt = 0; nt < 4; nt++)
        baseB[nt] = (uint32_t)(16384 + (wn * 32 + nt * 8 + l7) * 128);

    float acc[4][4][4];
#pragma unroll
    for (int mt = 0; mt < 4; mt++)
#pragma unroll
        for (int nt = 0; nt < 4; nt++)
#pragma unroll
            for (int i = 0; i < 4; i++) acc[mt][nt][i] = 0.0f;

    {
        const uint32_t sA = sbase, sB = sbase + 16384;
#pragma unroll
        for (int i = 0; i < 4; i++) {
            cp16(sA + dsw + i * 4096, Ag + (size_t)i * rstep);
            cp16(sB + dsw + i * 4096, Bg + (size_t)i * rstep);
        }
        CP_COMMIT();
    }

    for (int t = 0; t < NT_; t++) {
        CP_WAIT0();
        __syncthreads();
        if (t + 1 < NT_) {
            const uint32_t so = ((t + 1) & 1) * 32768u;
            const char* ga = Ag + (size_t)(t + 1) * 128;
            const char* gb = Bg + (size_t)(t + 1) * 128;
#pragma unroll
            for (int i = 0; i < 4; i++) {
                cp16(sbase + so + dsw + i * 4096,          ga + (size_t)i * rstep);
                cp16(sbase + so + 16384 + dsw + i * 4096,  gb + (size_t)i * rstep);
            }
            CP_COMMIT();
        }
        const uint32_t bufo = sbase + (t & 1) * 32768u;
#pragma unroll
        for (int ks = 0; ks < 4; ks++) {
            const uint32_t axo = ((uint32_t)(ks * 32 + acg * 16)) ^ xrA;
            const uint32_t bxo = ((uint32_t)(ks * 32 + bcg * 16)) ^ xrB;
            uint32_t a[4][4], b[4][2];
#pragma unroll
            for (int mt = 0; mt < 4; mt++)
                LDX4(a[mt], bufo + baseA[mt] + axo);
#pragma unroll
            for (int nt = 0; nt < 4; nt++)
                LDX2(b[nt], bufo + baseB[nt] + bxo);
#pragma unroll
            for (int mt = 0; mt < 4; mt++)
#pragma unroll
                for (int nt = 0; nt < 4; nt++)
                    MMA16816(acc[mt][nt], a[mt], b[nt]);
        }
    }

    const int gid = lane >> 2, tig = lane & 3;
#pragma unroll
    for (int mt = 0; mt < 4; mt++) {
        const int r = m0 + wm * 64 + mt * 16 + gid;
#pragma unroll
        for (int nt = 0; nt < 4; nt++) {
            const int cc = n0 + wn * 32 + nt * 8 + 2 * tig;
            float2 v0 = make_float2(acc[mt][nt][0], acc[mt][nt][1]);
            float2 v1 = make_float2(acc[mt][nt][2], acc[mt][nt][3]);
            *(float2*)&C[(size_t)r * N + cc]       = v0;
            *(float2*)&C[(size_t)(r + 8) * N + cc] = v1;
        }
    }
}

// ===================== RoPE + bf16 hi/lo split ==============================
__global__ void rope_split_kernel(const float* __restrict__ qkv,
                                  __nv_bfloat16* __restrict__ q2,
                                  __nv_bfloat16* __restrict__ k2,
                                  __nv_bfloat16* __restrict__ v2)
{
    __shared__ float s[64][132];
    const int bid = blockIdx.x;
    const int tt = bid & 7;
    const int h  = (bid >> 3) & 15;
    const int b  = bid >> 7;
    const int t0 = tt << 6;
    const int tid = threadIdx.x;
    const int bh = b * H_ + h;

    for (int which = 0; which < 3; which++) {
        __nv_bfloat16* dst = (which == 0) ? q2 : (which == 1) ? k2 : v2;
#pragma unroll
        for (int p = 0; p < 8; p++) {
            const int idx = tid + (p << 8);
            const int r  = idx >> 5;
            const int c4 = (idx & 31) << 2;
            const float4 v = *(const float4*)
                &qkv[((size_t)((b * T_ + t0 + r) * 3 + which)) * C_ + h * HD_ + c4];
            s[r][c4+0] = v.x; s[r][c4+1] = v.y; s[r][c4+2] = v.z; s[r][c4+3] = v.w;
        }
        __syncthreads();
        if (which < 2) {
            for (int it = tid; it < 512; it += 256) {
                const int r = it >> 3, d = it & 7;
                const float x1 = s[r][d], x2 = s[r][d + 8];
                const float inv = powf(10000.0f, -(float)d * 0.125f);
                const float ang = (float)(t0 + r) * inv;
                float sn, cs;
                sincosf(ang, &sn, &cs);
                s[r][d]     = x1 * cs - x2 * sn;
                s[r][d + 8] = x2 * cs + x1 * sn;
            }
        }
        __syncthreads();
#pragma unroll
        for (int p = 0; p < 8; p++) {
            const int idx = tid + (p << 8);
            const int r  = idx >> 5;
            const int c4 = (idx & 31) << 2;
            const float v0 = s[r][c4], v1 = s[r][c4+1], v2f = s[r][c4+2], v3 = s[r][c4+3];
            const float h0 = bf16_round(v0), h1 = bf16_round(v1);
            const float h2 = bf16_round(v2f), h3 = bf16_round(v3);
            uint2 hp, lp;
            hp.x = pack2(h0, h1); hp.y = pack2(h2, h3);
            lp.x = pack2(v0 - h0, v1 - h1); lp.y = pack2(v2f - h2, v3 - h3);
            __nv_bfloat16* row = dst + ((size_t)bh * T_ + t0 + r) * 256;
            *(uint2*)(row + c4)       = hp;
            *(uint2*)(row + 128 + c4) = lp;
        }
        __syncthreads();
    }
}

// ===================== tensor-core flash attention ==========================
// Block: 128 q-rows (8 warps x 16 rows, warp-local softmax), k-tiles of 64.
// S = Qh*Kh + Ql*Kh + Qh*Kl ; O += Ph*Vh + Pl*Vh + Ph*Vl  (all fp32 accum).
#define APITCH 136           // bf16 elems/row (272 B) -> conflict-free LDSM
#define OPITCH 132
#define SQH 0
#define SQL 34816
#define SKH 69632
#define SKL 87040
#define SVH 104448
#define SVL 121856
#define SOST 69632           // O staging reuses K/V region
#define ATTN_SMEM 139264

__global__ __launch_bounds__(256, 1)
void attention_tc(const __nv_bfloat16* __restrict__ q2,
                  const __nv_bfloat16* __restrict__ k2,
                  const __nv_bfloat16* __restrict__ v2,
                  __nv_bfloat16* __restrict__ y2)
{
    extern __shared__ char sm[];
    const uint32_t sb = smem_u32(sm);
    const int bid  = blockIdx.x;
    const int qblk = bid & 3;
    const int h    = (bid >> 2) & 15;
    const int b    = bid >> 6;
    const int bh   = b * H_ + h;
    const int q0   = qblk << 7;
    const int tid  = threadIdx.x;
    const int w    = tid >> 5, lane = tid & 31;
    const int gid  = lane >> 2, tig = lane & 3;
    const int l15  = lane & 15;
    const int acg  = (lane >> 4) & 1;
    const int l7   = lane & 7;
    const int bcg  = (lane >> 3) & 1;
    const float scale = 0.088388347648318447f;   // 1/sqrt(128)

    // ---- load Q tile (128 rows x 512B) into QH/QL
    {
        const char* src = (const char*)(q2 + ((size_t)bh * T_ + q0) * 256);
#pragma unroll
        for (int p = 0; p < 16; p++) {
            const int idx = tid + (p << 8);
            const int r = idx >> 5, seg = idx & 31;
            const uint4 v = *(const uint4*)(src + (size_t)r * 512 + seg * 16);
            const int off = (r * APITCH + (seg & 15) * 8) * 2;
            *(uint4*)(sm + ((seg < 16) ? SQH : SQL) + off) = v;
        }
    }

    float m0r = -INFINITY, m1r = -INFINITY, l0 = 0.0f, l1 = 0.0f;
    float oacc[16][4];
#pragma unroll
    for (int nt = 0; nt < 16; nt++)
#pragma unroll
        for (int i = 0; i < 4; i++) oacc[nt][i] = 0.0f;

    const uint32_t arow2 = (uint32_t)(((w << 4) + l15) * APITCH) * 2;

    const int nkt = (qblk << 1) + 2;
    for (int kt = 0; kt < nkt; kt++) {
        const int c0 = kt << 6;
        __syncthreads();   // previous compute done before K/V overwrite
        {
            const char* ks = (const char*)(k2 + ((size_t)bh * T_ + c0) * 256);
            const char* vs = (const char*)(v2 + ((size_t)bh * T_ + c0) * 256);
#pragma unroll
            for (int p = 0; p < 8; p++) {
                const int idx = tid + (p << 8);
                const int r = idx >> 5, seg = idx & 31;
                const uint4 kv = *(const uint4*)(ks + (size_t)r * 512 + seg * 16);
                const uint4 vv = *(const uint4*)(vs + (size_t)r * 512 + seg * 16);
                const int off = (r * APITCH + (seg & 15) * 8) * 2;
                if (seg < 16) { *(uint4*)(sm + SKH + off) = kv; *(uint4*)(sm + SVH + off) = vv; }
                else          { *(uint4*)(sm + SKL + off) = kv; *(uint4*)(sm + SVL + off) = vv; }
            }
        }
        __syncthreads();   // tiles ready (covers Q load on iter 0)

        const bool skip = (q0 + (w << 4) + 15) < c0;   // warp fully masked
        if (!skip) {
            // ---- S = scale * Q K^T over split parts
            float sacc[8][4];
#pragma unroll
            for (int nt = 0; nt < 8; nt++)
#pragma unroll
                for (int i = 0; i < 4; i++) sacc[nt][i] = 0.0f;

#pragma unroll
            for (int j = 0; j < 8; j++) {
                const uint32_t ka = (uint32_t)(j * 32 + acg * 16);
                const uint32_t kb = (uint32_t)(j * 32 + bcg * 16);
                uint32_t ah[4], alr[4];
                LDX4(ah,  sb + SQH + arow2 + ka);
                LDX4(alr, sb + SQL + arow2 + ka);
#pragma unroll
                for (int nt = 0; nt < 8; nt++) {
                    uint32_t bb[2];
                    LDX2(bb, sb + SKH + (uint32_t)(((nt << 3) + l7) * APITCH) * 2 + kb);
                    MMA16816(sacc[nt], ah,  bb);
                    MMA16816(sacc[nt], alr, bb);
                }
            }
#pragma unroll
            for (int j = 0; j < 8; j++) {
                const uint32_t ka = (uint32_t)(j * 32 + acg * 16);
                const uint32_t kb = (uint32_t)(j * 32 + bcg * 16);
                uint32_t ah[4];
                LDX4(ah, sb + SQH + arow2 + ka);
#pragma unroll
                for (int nt = 0; nt < 8; nt++) {
                    uint32_t bb[2];
                    LDX2(bb, sb + SKL + (uint32_t)(((nt << 3) + l7) * APITCH) * 2 + kb);
                    MMA16816(sacc[nt], ah, bb);
                }
            }

            // ---- mask + online softmax (warp-local, rows gid & gid+8)
            const int r0g = q0 + (w << 4) + gid;
            const int r1g = r0g + 8;
            float mx0 = -INFINITY, mx1 = -INFINITY;
#pragma unroll
            for (int nt = 0; nt < 8; nt++) {
                const int cb = c0 + (nt << 3) + (tig << 1);
#pragma unroll
                for (int e = 0; e < 2; e++) {
                    float s0 = sacc[nt][e] * scale;
                    if (cb + e > r0g) s0 = -INFINITY;
                    sacc[nt][e] = s0; mx0 = fmaxf(mx0, s0);
                    float s1 = sacc[nt][2 + e] * scale;
                    if (cb + e > r1g) s1 = -INFINITY;
                    sacc[nt][2 + e] = s1; mx1 = fmaxf(mx1, s1);
                }
            }
            mx0 = fmaxf(mx0, __shfl_xor_sync(0xffffffffu, mx0, 1));
            mx0 = fmaxf(mx0, __shfl_xor_sync(0xffffffffu, mx0, 2));
            mx1 = fmaxf(mx1, __shfl_xor_sync(0xffffffffu, mx1, 1));
            mx1 = fmaxf(mx1, __shfl_xor_sync(0xffffffffu, mx1, 2));
            const float mn0 = fmaxf(m0r, mx0), mn1 = fmaxf(m1r, mx1);
            const float al0 = __expf(m0r - mn0), al1 = __expf(m1r - mn1);
            m0r = mn0; m1r = mn1;
            float sum0 = 0.0f, sum1 = 0.0f;
#pragma unroll
            for (int nt = 0; nt < 8; nt++) {
#pragma unroll
                for (int e = 0; e < 2; e++) {
                    const float p0 = __expf(sacc[nt][e] - mn0);
                    sacc[nt][e] = p0; sum0 += p0;
                    const float p1 = __expf(sacc[nt][2 + e] - mn1);
                    sacc[nt][2 + e] = p1; sum1 += p1;
                }
            }
            sum0 += __shfl_xor_sync(0xffffffffu, sum0, 1);
            sum0 += __shfl_xor_sync(0xffffffffu, sum0, 2);
            sum1 += __shfl_xor_sync(0xffffffffu, sum1, 1);
            sum1 += __shfl_xor_sync(0xffffffffu, sum1, 2);
            l0 = l0 * al0 + sum0;
            l1 = l1 * al1 + sum1;
#pragma unroll
            for (int nt = 0; nt < 16; nt++) {
                oacc[nt][0] *= al0; oacc[nt][1] *= al0;
                oacc[nt][2] *= al1; oacc[nt][3] *= al1;
            }

            // ---- P -> A fragments (hi + lo), in registers
            uint32_t ph[4][4], pl[4][4];
#pragma unroll
            for (int j = 0; j < 4; j++) {
                const float* s0 = sacc[2 * j];
                const float* s1 = sacc[2 * j + 1];
                const float h00 = bf16_round(s0[0]), h01 = bf16_round(s0[1]);
                const float h02 = bf16_round(s0[2]), h03 = bf16_round(s0[3]);
                const float h10 = bf16_round(s1[0]), h11 = bf16_round(s1[1]);
                const float h12 = bf16_round(s1[2]), h13 = bf16_round(s1[3]);
                ph[j][0] = pack2(h00, h01);
                ph[j][1] = pack2(h02, h03);
                ph[j][2] = pack2(h10, h11);
                ph[j][3] = pack2(h12, h13);
                pl[j][0] = pack2(s0[0] - h00, s0[1] - h01);
                pl[j][1] = pack2(s0[2] - h02, s0[3] - h03);
                pl[j][2] = pack2(s1[0] - h10, s1[1] - h11);
                pl[j][3] = pack2(s1[2] - h12, s1[3] - h13);
            }

            // ---- O += P @ V (3-split)
#pragma unroll
            for (int j = 0; j < 4; j++) {
                const uint32_t va = (uint32_t)(((j << 4) + l15) * APITCH) * 2;
#pragma unroll
                for (int nt = 0; nt < 16; nt++) {
                    uint32_t bhv[2], blv[2];
                    LDX2T(bhv, sb + SVH + va + (uint32_t)(nt << 4));
                    LDX2T(blv, sb + SVL + va + (uint32_t)(nt << 4));
                    MMA16816(oacc[nt], ph[j], bhv);
                    MMA16816(oacc[nt], pl[j], bhv);
                    MMA16816(oacc[nt], ph[j], blv);
                }
            }
        }
    }
    __syncthreads();   // all compute done before O staging overwrites K/V smem

    // ---- normalize + stage O in smem (reuse K/V region)
    {
        float* Ost = (float*)(sm + SOST);
        const float iv0 = 1.0f / l0, iv1 = 1.0f / l1;
        const int rl0 = (w << 4) + gid, rl1 = rl0 + 8;
#pragma unroll
        for (int nt = 0; nt < 16; nt++) {
            const int cc = (nt << 3) + (tig << 1);
            Ost[rl0 * OPITCH + cc]     = oacc[nt][0] * iv0;
            Ost[rl0 * OPITCH + cc + 1] = oacc[nt][1] * iv0;
            Ost[rl1 * OPITCH + cc]     = oacc[nt][2] * iv1;
            Ost[rl1 * OPITCH + cc + 1] = oacc[nt][3] * iv1;
        }
    }
    __syncthreads();

    // ---- write y2 hi/lo split [M, 6144]
    {
        const float* Ost = (const float*)(sm + SOST);
        const int kcb = h * HD_;
#pragma unroll
        for (int p = 0; p < 16; p++) {
            const int idx = tid + (p << 8);
            const int r = idx >> 5, c4 = (idx & 31) << 2;
            const float v0 = Ost[r * OPITCH + c4],     v1 = Ost[r * OPITCH + c4 + 1];
            const float v2f = Ost[r * OPITCH + c4 + 2], v3 = Ost[r * OPITCH + c4 + 3];
            const float h0 = bf16_round(v0), h1 = bf16_round(v1);
            const float h2 = bf16_round(v2f), h3 = bf16_round(v3);
            uint2 hp, lp;
            hp.x = pack2(h0, h1); hp.y = pack2(h2, h3);
            lp.x = pack2(v0 - h0, v1 - h1); lp.y = pack2(v2f - h2, v3 - h3);
            const size_t ro = (size_t)(b * T_ + q0 + r) * K3_;
            *(uint2*)&y2[ro + kcb + c4]        = hp;
            *(uint2*)&y2[ro + 2048 + kcb + c4] = lp;
            *(uint2*)&y2[ro + 4096 + kcb + c4] = hp;
        }
    }
}

// ---------------------------------------------------------------------------
extern "C" void kernel_launch(void* const* d_in, const int* in_sizes, int n_in,
                              void* d_out, int out_size)
{
    const float* x    = (const float*)d_in[0];   // [16,512,2048]
    const float* Wqkv = (const float*)d_in[1];   // [2048,6144]
    const float* Wout = (const float*)d_in[2];   // [2048,2048]
    float* out = (float*)d_out;                  // [16,512,2048]

    float *qkv;
    __nv_bfloat16 *q2, *k2, *v2, *a2, *b2q, *b2o, *y2;
    cudaGetSymbolAddress((void**)&qkv, g_qkv);
    cudaGetSymbolAddress((void**)&q2,  g_q2);
    cudaGetSymbolAddress((void**)&k2,  g_k2);
    cudaGetSymbolAddress((void**)&v2,  g_v2);
    cudaGetSymbolAddress((void**)&a2,  g_a2);
    cudaGetSymbolAddress((void**)&b2q, g_b2q);
    cudaGetSymbolAddress((void**)&b2o, g_b2o);
    cudaGetSymbolAddress((void**)&y2,  g_y2);

    // 0) bf16 hi/lo conversions
    conv_a_kernel<<<(M_ * C_) / 1024, 256>>>(x, a2);
    conv_w_kernel<<<dim3(N3_ / 32, C_ / 32), 256>>>(Wqkv, b2q, N3_);
    conv_w_kernel<<<dim3(C_ / 32,  C_ / 32), 256>>>(Wout, b2o, C_);

    cudaFuncSetAttribute(gemm_mma, cudaFuncAttributeMaxDynamicSharedMemorySize, G_SMEM_BYTES);

    // 1) qkv = x @ Wqkv   (mma.sync bf16 3-split)
    gemm_mma<<<dim3(N3_ / 128, M_ / 128), 256, G_SMEM_BYTES>>>(a2, b2q, qkv, N3_);

    // 2) RoPE + split q,k,v -> bf16 hi/lo [B,H,T,256]
    rope_split_kernel<<<B_ * H_ * (T_ / 64), 256>>>(qkv, q2, k2, v2);

    // 3) tensor-core causal flash attention -> y2 (split layout)
    cudaFuncSetAttribute(attention_tc, cudaFuncAttributeMaxDynamicSharedMemorySize, ATTN_SMEM);
    attention_tc<<<B_ * H_ * 4, 256, ATTN_SMEM>>>(q2, k2, v2, y2);

    // 4) out = y @ Wout   (mma.sync bf16 3-split)
    gemm_mma<<<dim3(C_ / 128, M_ / 128), 256, G_SMEM_BYTES>>>(y2, b2o, out, C_);
}

// round 12
// speedup vs baseline: 2.4996x; 1.0036x over previous
#include <cuda_runtime.h>
#include <cuda_bf16.h>
#include <math.h>
#include <stdint.h>

// Problem dims
#define B_   16
#define T_   512
#define C_   2048
#define H_   16
#define HD_  128
#define N3_  6144   // 3*C
#define M_   8192   // B*T
#define K3_  6144   // split-K (hi|lo|hi concatenation) for both GEMMs
#define KC_  64
#define NT_  (K3_ / KC_)

// ---------------- scratch (device globals; no runtime allocation) ----------
__device__ float          g_qkv  [(size_t)M_ * N3_];            // [B*T, 3*C] fp32
__device__ __nv_bfloat16  g_q2   [(size_t)B_ * H_ * T_ * 256];  // [B,H,T, hi128|lo128]
__device__ __nv_bfloat16  g_k2   [(size_t)B_ * H_ * T_ * 256];
__device__ __nv_bfloat16  g_v2   [(size_t)B_ * H_ * T_ * 256];
__device__ __nv_bfloat16  g_a2   [(size_t)M_ * K3_];            // [M, 3K] = [x_hi | x_lo | x_hi]
__device__ __nv_bfloat16  g_b2q  [(size_t)N3_ * K3_];           // [6144, 3K] = [W_hi | W_hi | W_lo]
__device__ __nv_bfloat16  g_b2o  [(size_t)C_ * K3_];            // [2048, 3K]
__device__ __nv_bfloat16  g_y2   [(size_t)M_ * K3_];            // attention out, split layout

// ===================== helpers ==============================================
__device__ __forceinline__ uint32_t smem_u32(const void* p) {
    uint32_t a;
    asm("{ .reg .u64 t; cvta.to.shared.u64 t, %1; cvt.u32.u64 %0, t; }" : "=r"(a) : "l"(p));
    return a;
}
__device__ __forceinline__ void cp16(uint32_t dst, const void* src) {
    asm volatile("cp.async.cg.shared.global [%0], [%1], 16;" :: "r"(dst), "l"(src));
}
#define CP_COMMIT()  asm volatile("cp.async.commit_group;" ::: "memory")
#define CP_WAIT1()   asm volatile("cp.async.wait_group 1;" ::: "memory")
#define SW128(off) ((off) ^ (((off) >> 3) & 0x70))

#define LDX4(a, addr) asm volatile( \
    "ldmatrix.sync.aligned.m8n8.x4.shared.b16 {%0,%1,%2,%3}, [%4];" \
    : "=r"((a)[0]), "=r"((a)[1]), "=r"((a)[2]), "=r"((a)[3]) : "r"(addr))
#define LDX2(bq, addr) asm volatile( \
    "ldmatrix.sync.aligned.m8n8.x2.shared.b16 {%0,%1}, [%2];" \
    : "=r"((bq)[0]), "=r"((bq)[1]) : "r"(addr))
#define LDX2T(bq, addr) asm volatile( \
    "ldmatrix.sync.aligned.m8n8.x2.trans.shared.b16 {%0,%1}, [%2];" \
    : "=r"((bq)[0]), "=r"((bq)[1]) : "r"(addr))
#define MMA16816(c, a, bq) asm volatile( \
    "mma.sync.aligned.m16n8k16.row.col.f32.bf16.bf16.f32 " \
    "{%0,%1,%2,%3}, {%4,%5,%6,%7}, {%8,%9}, {%0,%1,%2,%3};" \
    : "+f"((c)[0]), "+f"((c)[1]), "+f"((c)[2]), "+f"((c)[3]) \
    : "r"((a)[0]), "r"((a)[1]), "r"((a)[2]), "r"((a)[3]), "r"((bq)[0]), "r"((bq)[1]))

__device__ __forceinline__ uint32_t pack2(float a, float b) {
    __nv_bfloat162 t = __floats2bfloat162_rn(a, b);
    return *reinterpret_cast<uint32_t*>(&t);
}
__device__ __forceinline__ float bf16_round(float a) {
    return __bfloat162float(__float2bfloat16(a));
}

// ===================== conversion kernels ===================================
__global__ void conv_a_kernel(const float* __restrict__ X, __nv_bfloat16* __restrict__ A2)
{
    const int idx = blockIdx.x * 256 + threadIdx.x;
    const int e = idx << 2;
    const int m = e >> 11;
    const int k = e & 2047;
    const float4 v = *(const float4*)&X[(size_t)e];
    const float h0 = bf16_round(v.x), h1 = bf16_round(v.y);
    const float h2 = bf16_round(v.z), h3 = bf16_round(v.w);
    uint2 hp, lp;
    hp.x = pack2(h0, h1); hp.y = pack2(h2, h3);
    lp.x = pack2(v.x - h0, v.y - h1); lp.y = pack2(v.z - h2, v.w - h3);
    const size_t ro = (size_t)m * K3_;
    *(uint2*)&A2[ro + k]        = hp;
    *(uint2*)&A2[ro + 2048 + k] = lp;
    *(uint2*)&A2[ro + 4096 + k] = hp;
}

__global__ void conv_w_kernel(const float* __restrict__ W, __nv_bfloat16* __restrict__ B2, int N)
{
    __shared__ float tile[32][33];
    const int n0 = blockIdx.x << 5;
    const int k0 = blockIdx.y << 5;
    const int tid = threadIdx.x;
    const int c = tid & 31, rb = tid >> 5;
#pragma unroll
    for (int j = 0; j < 4; j++) {
        const int r = rb + (j << 3);
        tile[r][c] = W[(size_t)(k0 + r) * N + n0 + c];
    }
    __syncthreads();
#pragma unroll
    for (int j = 0; j < 4; j++) {
        const int nl = rb + (j << 3);
        const int kl = c;
        const float v = tile[kl][nl];
        const float h = bf16_round(v);
        const __nv_bfloat16 hb = __float2bfloat16(h);
        const __nv_bfloat16 lb = __float2bfloat16(v - h);
        const size_t ro = (size_t)(n0 + nl) * K3_ + k0 + kl;
        B2[ro]        = hb;
        B2[ro + 2048] = hb;
        B2[ro + 4096] = lb;
    }
}

// ===================== bf16 mma.sync GEMM (3-stage cp.async) ================
#define G_SMEM_BYTES (3 * 32768)

__global__ __launch_bounds__(256, 2)
void gemm_mma(const __nv_bfloat16* __restrict__ A,
              const __nv_bfloat16* __restrict__ Bt,
              float* __restrict__ C, int N)
{
    extern __shared__ char sm[];
    const uint32_t sbase = smem_u32(sm);
    const int tid  = threadIdx.x;
    const int lane = tid & 31;
    const int w    = tid >> 5;
    const int wm   = w >> 2;
    const int wn   = w & 3;
    const int m0 = blockIdx.y << 7;
    const int n0 = blockIdx.x << 7;

    const int r0  = tid >> 3;
    const int c16 = tid & 7;
    const uint32_t dsw = SW128((uint32_t)(r0 * 128 + c16 * 16));
    const char* Ag = (const char*)(A  + (size_t)(m0 + r0) * K3_) + c16 * 16;
    const char* Bg = (const char*)(Bt + (size_t)(n0 + r0) * K3_) + c16 * 16;
    const size_t rstep = (size_t)32 * K3_ * 2;

    const int l15 = lane & 15;
    const int acg = (lane >> 4) & 1;
    const int l7  = lane & 7;
    const int bcg = (lane >> 3) & 1;
    const uint32_t xrA = (uint32_t)((l15 & 7) << 4);
    const uint32_t xrB = (uint32_t)(l7 << 4);
    uint32_t baseA[4], baseB[4];
#pragma unroll
    for (int mt = 0; mt < 4; mt++)
        baseA[mt] = (uint32_t)((wm * 64 + mt * 16 + l15) * 128);
#pragma unroll
    for (int nt = 0; nt < 4; nt++)
        baseB[nt] = (uint32_t)(16384 + (wn * 32 + nt * 8 + l7) * 128);

    float acc[4][4][4];
#pragma unroll
    for (int mt = 0; mt < 4; mt++)
#pragma unroll
        for (int nt = 0; nt < 4; nt++)
#pragma unroll
            for (int i = 0; i < 4; i++) acc[mt][nt][i] = 0.0f;

    // ---- prologue: stage chunks 0 and 1 into buffers 0 and 1
#pragma unroll
    for (int pt = 0; pt < 2; pt++) {
        const uint32_t so = (uint32_t)pt * 32768u;
        const char* ga = Ag + (size_t)pt * 128;
        const char* gb = Bg + (size_t)pt * 128;
#pragma unroll
        for (int i = 0; i < 4; i++) {
            cp16(sbase + so + dsw + i * 4096,          ga + (size_t)i * rstep);
            cp16(sbase + so + 16384 + dsw + i * 4096,  gb + (size_t)i * rstep);
        }
        CP_COMMIT();
    }

    int buf = 0, nbuf = 2;   // compute buffer index (t%3), next-load buffer ((t+2)%3)
    for (int t = 0; t < NT_; t++) {
        CP_WAIT1();          // oldest pending group (chunk t) complete
        __syncthreads();     // all warps past chunk t-1 compute -> safe to refill buf (t+2)%3
        {
            // issue chunk t+2 (empty commit on tail keeps group count exact)
            if (t + 2 < NT_) {
                const uint32_t so = (uint32_t)nbuf * 32768u;
                const char* ga = Ag + (size_t)(t + 2) * 128;
                const char* gb = Bg + (size_t)(t + 2) * 128;
#pragma unroll
                for (int i = 0; i < 4; i++) {
                    cp16(sbase + so + dsw + i * 4096,          ga + (size_t)i * rstep);
                    cp16(sbase + so + 16384 + dsw + i * 4096,  gb + (size_t)i * rstep);
                }
            }
            CP_COMMIT();
        }
        const uint32_t bufo = sbase + (uint32_t)buf * 32768u;
#pragma unroll
        for (int ks = 0; ks < 4; ks++) {
            const uint32_t axo = ((uint32_t)(ks * 32 + acg * 16)) ^ xrA;
            const uint32_t bxo = ((uint32_t)(ks * 32 + bcg * 16)) ^ xrB;
            uint32_t a[4][4], b[4][2];
#pragma unroll
            for (int mt = 0; mt < 4; mt++)
                LDX4(a[mt], bufo + baseA[mt] + axo);
#pragma unroll
            for (int nt = 0; nt < 4; nt++)
                LDX2(b[nt], bufo + baseB[nt] + bxo);
#pragma unroll
            for (int mt = 0; mt < 4; mt++)
#pragma unroll
                for (int nt = 0; nt < 4; nt++)
                    MMA16816(acc[mt][nt], a[mt], b[nt]);
        }
        buf  = (buf  == 2) ? 0 : buf + 1;
        nbuf = (nbuf == 2) ? 0 : nbuf + 1;
    }

    const int gid = lane >> 2, tig = lane & 3;
#pragma unroll
    for (int mt = 0; mt < 4; mt++) {
        const int r = m0 + wm * 64 + mt * 16 + gid;
#pragma unroll
        for (int nt = 0; nt < 4; nt++) {
            const int cc = n0 + wn * 32 + nt * 8 + 2 * tig;
            float2 v0 = make_float2(acc[mt][nt][0], acc[mt][nt][1]);
            float2 v1 = make_float2(acc[mt][nt][2], acc[mt][nt][3]);
            *(float2*)&C[(size_t)r * N + cc]       = v0;
            *(float2*)&C[(size_t)(r + 8) * N + cc] = v1;
        }
    }
}

// ===================== RoPE + bf16 hi/lo split ==============================
__global__ void rope_split_kernel(const float* __restrict__ qkv,
                                  __nv_bfloat16* __restrict__ q2,
                                  __nv_bfloat16* __restrict__ k2,
                                  __nv_bfloat16* __restrict__ v2)
{
    __shared__ float s[64][132];
    const int bid = blockIdx.x;
    const int tt = bid & 7;
    const int h  = (bid >> 3) & 15;
    const int b  = bid >> 7;
    const int t0 = tt << 6;
    const int tid = threadIdx.x;
    const int bh = b * H_ + h;

    for (int which = 0; which < 3; which++) {
        __nv_bfloat16* dst = (which == 0) ? q2 : (which == 1) ? k2 : v2;
#pragma unroll
        for (int p = 0; p < 8; p++) {
            const int idx = tid + (p << 8);
            const int r  = idx >> 5;
            const int c4 = (idx & 31) << 2;
            const float4 v = *(const float4*)
                &qkv[((size_t)((b * T_ + t0 + r) * 3 + which)) * C_ + h * HD_ + c4];
            s[r][c4+0] = v.x; s[r][c4+1] = v.y; s[r][c4+2] = v.z; s[r][c4+3] = v.w;
        }
        __syncthreads();
        if (which < 2) {
            for (int it = tid; it < 512; it += 256) {
                const int r = it >> 3, d = it & 7;
                const float x1 = s[r][d], x2 = s[r][d + 8];
                const float inv = powf(10000.0f, -(float)d * 0.125f);
                const float ang = (float)(t0 + r) * inv;
                float sn, cs;
                sincosf(ang, &sn, &cs);
                s[r][d]     = x1 * cs - x2 * sn;
                s[r][d + 8] = x2 * cs + x1 * sn;
            }
        }
        __syncthreads();
#pragma unroll
        for (int p = 0; p < 8; p++) {
            const int idx = tid + (p << 8);
            const int r  = idx >> 5;
            const int c4 = (idx & 31) << 2;
            const float v0 = s[r][c4], v1 = s[r][c4+1], v2f = s[r][c4+2], v3 = s[r][c4+3];
            const float h0 = bf16_round(v0), h1 = bf16_round(v1);
            const float h2 = bf16_round(v2f), h3 = bf16_round(v3);
            uint2 hp, lp;
            hp.x = pack2(h0, h1); hp.y = pack2(h2, h3);
            lp.x = pack2(v0 - h0, v1 - h1); lp.y = pack2(v2f - h2, v3 - h3);
            __nv_bfloat16* row = dst + ((size_t)bh * T_ + t0 + r) * 256;
            *(uint2*)(row + c4)       = hp;
            *(uint2*)(row + 128 + c4) = lp;
        }
        __syncthreads();
    }
}

// ===================== tensor-core flash attention ==========================
// Block: 128 q-rows (8 warps x 16 rows, warp-local softmax), k-tiles of 64.
// S = Qh*Kh + Ql*Kh + Qh*Kl ; O += Ph*Vh + Pl*Vh + Ph*Vl  (all fp32 accum).
#define APITCH 136           // bf16 elems/row (272 B) -> conflict-free LDSM
#define OPITCH 132
#define SQH 0
#define SQL 34816
#define SKH 69632
#define SKL 87040
#define SVH 104448
#define SVL 121856
#define SOST 69632           // O staging reuses K/V region
#define ATTN_SMEM 139264

__global__ __launch_bounds__(256, 1)
void attention_tc(const __nv_bfloat16* __restrict__ q2,
                  const __nv_bfloat16* __restrict__ k2,
                  const __nv_bfloat16* __restrict__ v2,
                  __nv_bfloat16* __restrict__ y2)
{
    extern __shared__ char sm[];
    const uint32_t sb = smem_u32(sm);
    const int bid  = blockIdx.x;
    const int qblk = bid & 3;
    const int h    = (bid >> 2) & 15;
    const int b    = bid >> 6;
    const int bh   = b * H_ + h;
    const int q0   = qblk << 7;
    const int tid  = threadIdx.x;
    const int w    = tid >> 5, lane = tid & 31;
    const int gid  = lane >> 2, tig = lane & 3;
    const int l15  = lane & 15;
    const int acg  = (lane >> 4) & 1;
    const int l7   = lane & 7;
    const int bcg  = (lane >> 3) & 1;
    const float scale = 0.088388347648318447f;   // 1/sqrt(128)

    // ---- load Q tile (128 rows x 512B) into QH/QL
    {
        const char* src = (const char*)(q2 + ((size_t)bh * T_ + q0) * 256);
#pragma unroll
        for (int p = 0; p < 16; p++) {
            const int idx = tid + (p << 8);
            const int r = idx >> 5, seg = idx & 31;
            const uint4 v = *(const uint4*)(src + (size_t)r * 512 + seg * 16);
            const int off = (r * APITCH + (seg & 15) * 8) * 2;
            *(uint4*)(sm + ((seg < 16) ? SQH : SQL) + off) = v;
        }
    }

    float m0r = -INFINITY, m1r = -INFINITY, l0 = 0.0f, l1 = 0.0f;
    float oacc[16][4];
#pragma unroll
    for (int nt = 0; nt < 16; nt++)
#pragma unroll
        for (int i = 0; i < 4; i++) oacc[nt][i] = 0.0f;

    const uint32_t arow2 = (uint32_t)(((w << 4) + l15) * APITCH) * 2;

    const int nkt = (qblk << 1) + 2;
    for (int kt = 0; kt < nkt; kt++) {
        const int c0 = kt << 6;
        __syncthreads();   // previous compute done before K/V overwrite
        {
            const char* ks = (const char*)(k2 + ((size_t)bh * T_ + c0) * 256);
            const char* vs = (const char*)(v2 + ((size_t)bh * T_ + c0) * 256);
#pragma unroll
            for (int p = 0; p < 8; p++) {
                const int idx = tid + (p << 8);
                const int r = idx >> 5, seg = idx & 31;
                const uint4 kv = *(const uint4*)(ks + (size_t)r * 512 + seg * 16);
                const uint4 vv = *(const uint4*)(vs + (size_t)r * 512 + seg * 16);
                const int off = (r * APITCH + (seg & 15) * 8) * 2;
                if (seg < 16) { *(uint4*)(sm + SKH + off) = kv; *(uint4*)(sm + SVH + off) = vv; }
                else          { *(uint4*)(sm + SKL + off) = kv; *(uint4*)(sm + SVL + off) = vv; }
            }
        }
        __syncthreads();   // tiles ready (covers Q load on iter 0)

        const bool skip = (q0 + (w << 4) + 15) < c0;   // warp fully masked
        if (!skip) {
            // ---- S = scale * Q K^T over split parts
            float sacc[8][4];
#pragma unroll
            for (int nt = 0; nt < 8; nt++)
#pragma unroll
                for (int i = 0; i < 4; i++) sacc[nt][i] = 0.0f;

#pragma unroll
            for (int j = 0; j < 8; j++) {
                const uint32_t ka = (uint32_t)(j * 32 + acg * 16);
                const uint32_t kb = (uint32_t)(j * 32 + bcg * 16);
                uint32_t ah[4], alr[4];
                LDX4(ah,  sb + SQH + arow2 + ka);
                LDX4(alr, sb + SQL + arow2 + ka);
#pragma unroll
                for (int nt = 0; nt < 8; nt++) {
                    uint32_t bb[2];
                    LDX2(bb, sb + SKH + (uint32_t)(((nt << 3) + l7) * APITCH) * 2 + kb);
                    MMA16816(sacc[nt], ah,  bb);
                    MMA16816(sacc[nt], alr, bb);
                }
            }
#pragma unroll
            for (int j = 0; j < 8; j++) {
                const uint32_t ka = (uint32_t)(j * 32 + acg * 16);
                const uint32_t kb = (uint32_t)(j * 32 + bcg * 16);
                uint32_t ah[4];
                LDX4(ah, sb + SQH + arow2 + ka);
#pragma unroll
                for (int nt = 0; nt < 8; nt++) {
                    uint32_t bb[2];
                    LDX2(bb, sb + SKL + (uint32_t)(((nt << 3) + l7) * APITCH) * 2 + kb);
                    MMA16816(sacc[nt], ah, bb);
                }
            }

            // ---- mask + online softmax (warp-local, rows gid & gid+8)
            const int r0g = q0 + (w << 4) + gid;
            const int r1g = r0g + 8;
            float mx0 = -INFINITY, mx1 = -INFINITY;
#pragma unroll
            for (int nt = 0; nt < 8; nt++) {
                const int cb = c0 + (nt << 3) + (tig << 1);
#pragma unroll
                for (int e = 0; e < 2; e++) {
                    float s0 = sacc[nt][e] * scale;
                    if (cb + e > r0g) s0 = -INFINITY;
                    sacc[nt][e] = s0; mx0 = fmaxf(mx0, s0);
                    float s1 = sacc[nt][2 + e] * scale;
                    if (cb + e > r1g) s1 = -INFINITY;
                    sacc[nt][2 + e] = s1; mx1 = fmaxf(mx1, s1);
                }
            }
            mx0 = fmaxf(mx0, __shfl_xor_sync(0xffffffffu, mx0, 1));
            mx0 = fmaxf(mx0, __shfl_xor_sync(0xffffffffu, mx0, 2));
            mx1 = fmaxf(mx1, __shfl_xor_sync(0xffffffffu, mx1, 1));
            mx1 = fmaxf(mx1, __shfl_xor_sync(0xffffffffu, mx1, 2));
            const float mn0 = fmaxf(m0r, mx0), mn1 = fmaxf(m1r, mx1);
            const float al0 = __expf(m0r - mn0), al1 = __expf(m1r - mn1);
            m0r = mn0; m1r = mn1;
            float sum0 = 0.0f, sum1 = 0.0f;
#pragma unroll
            for (int nt = 0; nt < 8; nt++) {
#pragma unroll
                for (int e = 0; e < 2; e++) {
                    const float p0 = __expf(sacc[nt][e] - mn0);
                    sacc[nt][e] = p0; sum0 += p0;
                    const float p1 = __expf(sacc[nt][2 + e] - mn1);
                    sacc[nt][2 + e] = p1; sum1 += p1;
                }
            }
            sum0 += __shfl_xor_sync(0xffffffffu, sum0, 1);
            sum0 += __shfl_xor_sync(0xffffffffu, sum0, 2);
            sum1 += __shfl_xor_sync(0xffffffffu, sum1, 1);
            sum1 += __shfl_xor_sync(0xffffffffu, sum1, 2);
            l0 = l0 * al0 + sum0;
            l1 = l1 * al1 + sum1;
#pragma unroll
            for (int nt = 0; nt < 16; nt++) {
                oacc[nt][0] *= al0; oacc[nt][1] *= al0;
                oacc[nt][2] *= al1; oacc[nt][3] *= al1;
            }

            // ---- P -> A fragments (hi + lo), in registers
            uint32_t ph[4][4], pl[4][4];
#pragma unroll
            for (int j = 0; j < 4; j++) {
                const float* s0 = sacc[2 * j];
                const float* s1 = sacc[2 * j + 1];
                const float h00 = bf16_round(s0[0]), h01 = bf16_round(s0[1]);
                const float h02 = bf16_round(s0[2]), h03 = bf16_round(s0[3]);
                const float h10 = bf16_round(s1[0]), h11 = bf16_round(s1[1]);
                const float h12 = bf16_round(s1[2]), h13 = bf16_round(s1[3]);
                ph[j][0] = pack2(h00, h01);
                ph[j][1] = pack2(h02, h03);
                ph[j][2] = pack2(h10, h11);
                ph[j][3] = pack2(h12, h13);
                pl[j][0] = pack2(s0[0] - h00, s0[1] - h01);
                pl[j][1] = pack2(s0[2] - h02, s0[3] - h03);
                pl[j][2] = pack2(s1[0] - h10, s1[1] - h11);
                pl[j][3] = pack2(s1[2] - h12, s1[3] - h13);
            }

            // ---- O += P @ V (3-split)
#pragma unroll
            for (int j = 0; j < 4; j++) {
                const uint32_t va = (uint32_t)(((j << 4) + l15) * APITCH) * 2;
#pragma unroll
                for (int nt = 0; nt < 16; nt++) {
                    uint32_t bhv[2], blv[2];
                    LDX2T(bhv, sb + SVH + va + (uint32_t)(nt << 4));
                    LDX2T(blv, sb + SVL + va + (uint32_t)(nt << 4));
                    MMA16816(oacc[nt], ph[j], bhv);
                    MMA16816(oacc[nt], pl[j], bhv);
                    MMA16816(oacc[nt], ph[j], blv);
                }
            }
        }
    }
    __syncthreads();   // all compute done before O staging overwrites K/V smem

    // ---- normalize + stage O in smem (reuse K/V region)
    {
        float* Ost = (float*)(sm + SOST);
        const float iv0 = 1.0f / l0, iv1 = 1.0f / l1;
        const int rl0 = (w << 4) + gid, rl1 = rl0 + 8;
#pragma unroll
        for (int nt = 0; nt < 16; nt++) {
            const int cc = (nt << 3) + (tig << 1);
            Ost[rl0 * OPITCH + cc]     = oacc[nt][0] * iv0;
            Ost[rl0 * OPITCH + cc + 1] = oacc[nt][1] * iv0;
            Ost[rl1 * OPITCH + cc]     = oacc[nt][2] * iv1;
            Ost[rl1 * OPITCH + cc + 1] = oacc[nt][3] * iv1;
        }
    }
    __syncthreads();

    // ---- write y2 hi/lo split [M, 6144]
    {
        const float* Ost = (const float*)(sm + SOST);
        const int kcb = h * HD_;
#pragma unroll
        for (int p = 0; p < 16; p++) {
            const int idx = tid + (p << 8);
            const int r = idx >> 5, c4 = (idx & 31) << 2;
            const float v0 = Ost[r * OPITCH + c4],     v1 = Ost[r * OPITCH + c4 + 1];
            const float v2f = Ost[r * OPITCH + c4 + 2], v3 = Ost[r * OPITCH + c4 + 3];
            const float h0 = bf16_round(v0), h1 = bf16_round(v1);
            const float h2 = bf16_round(v2f), h3 = bf16_round(v3);
            uint2 hp, lp;
            hp.x = pack2(h0, h1); hp.y = pack2(h2, h3);
            lp.x = pack2(v0 - h0, v1 - h1); lp.y = pack2(v2f - h2, v3 - h3);
            const size_t ro = (size_t)(b * T_ + q0 + r) * K3_;
            *(uint2*)&y2[ro + kcb + c4]        = hp;
            *(uint2*)&y2[ro + 2048 + kcb + c4] = lp;
            *(uint2*)&y2[ro + 4096 + kcb + c4] = hp;
        }
    }
}

// ---------------------------------------------------------------------------
extern "C" void kernel_launch(void* const* d_in, const int* in_sizes, int n_in,
                              void* d_out, int out_size)
{
    const float* x    = (const float*)d_in[0];   // [16,512,2048]
    const float* Wqkv = (const float*)d_in[1];   // [2048,6144]
    const float* Wout = (const float*)d_in[2];   // [2048,2048]
    float* out = (float*)d_out;                  // [16,512,2048]

    float *qkv;
    __nv_bfloat16 *q2, *k2, *v2, *a2, *b2q, *b2o, *y2;
    cudaGetSymbolAddress((void**)&qkv, g_qkv);
    cudaGetSymbolAddress((void**)&q2,  g_q2);
    cudaGetSymbolAddress((void**)&k2,  g_k2);
    cudaGetSymbolAddress((void**)&v2,  g_v2);
    cudaGetSymbolAddress((void**)&a2,  g_a2);
    cudaGetSymbolAddress((void**)&b2q, g_b2q);
    cudaGetSymbolAddress((void**)&b2o, g_b2o);
    cudaGetSymbolAddress((void**)&y2,  g_y2);

    // 0) bf16 hi/lo conversions
    conv_a_kernel<<<(M_ * C_) / 1024, 256>>>(x, a2);
    conv_w_kernel<<<dim3(N3_ / 32, C_ / 32), 256>>>(Wqkv, b2q, N3_);
    conv_w_kernel<<<dim3(C_ / 32,  C_ / 32), 256>>>(Wout, b2o, C_);

    cudaFuncSetAttribute(gemm_mma, cudaFuncAttributeMaxDynamicSharedMemorySize, G_SMEM_BYTES);

    // 1) qkv = x @ Wqkv   (mma.sync bf16 3-split)
    gemm_mma<<<dim3(N3_ / 128, M_ / 128), 256, G_SMEM_BYTES>>>(a2, b2q, qkv, N3_);

    // 2) RoPE + split q,k,v -> bf16 hi/lo [B,H,T,256]
    rope_split_kernel<<<B_ * H_ * (T_ / 64), 256>>>(qkv, q2, k2, v2);

    // 3) tensor-core causal flash attention -> y2 (split layout)
    cudaFuncSetAttribute(attention_tc, cudaFuncAttributeMaxDynamicSharedMemorySize, ATTN_SMEM);
    attention_tc<<<B_ * H_ * 4, 256, ATTN_SMEM>>>(q2, k2, v2, y2);

    // 4) out = y @ Wout   (mma.sync bf16 3-split)
    gemm_mma<<<dim3(C_ / 128, M_ / 128), 256, G_SMEM_BYTES>>>(y2, b2o, out, C_);
}